// round 5
// baseline (speedup 1.0000x reference)
#include <cuda_runtime.h>
#include <cuda_bf16.h>

#define BB 32
#define TT 8
#define NN 512
#define FF 4
#define COC 12
#define L2E 1.4426950408889634f

// Scratch (__device__ globals; no allocation allowed)
__device__ float  g_wscr[68];              // [0:4) v_src, [4:8) v_dst, [8:56) M[f*12+g], [56:68) cx
__device__ float4 g_A[BB * TT * NN];       // full-mask sum_j f*x_j
__device__ float  g_S[BB * TT * NN];       // full-mask sum_j f
__device__ float  g_cS[BB * TT * NN];      // corrections (rare zeros)
__device__ float  g_cA[BB * TT * NN * 4];
__device__ float  g_gru[BB * TT * NN * FF];// conv input [B][8ch][512][4]
__device__ float4 g_cM[576];               // folded conv+linear weights [co][o][ci][kh] -> float4 over u
__device__ float  g_cB2[24];               // folded bias [co][o]

__device__ __forceinline__ float ex2f(float a) {
    float r;
    asm("ex2.approx.f32 %0, %1;" : "=f"(r) : "f"(a));
    return r;
}
__device__ __forceinline__ float sigm(float x) {
    float e = ex2f(-x * L2E);
    return __fdividef(1.f, 1.f + e);
}
__device__ __forceinline__ float tanh_(float x) {
    float e = ex2f(x * (2.f * L2E));
    return __fdividef(e - 1.f, e + 1.f);
}
__device__ __forceinline__ unsigned int fmono(float f) {
    unsigned int u = __float_as_uint(f);
    return (u & 0x80000000u) ? ~u : (u | 0x80000000u);
}

// ---------------- K0: fold weights ----------------
__global__ void k_prep(const float* __restrict__ gatW, const float* __restrict__ attS,
                       const float* __restrict__ attD, const float* __restrict__ gatB,
                       const float* __restrict__ Wih, const float* __restrict__ bih,
                       const float* __restrict__ convW, const float* __restrict__ convB,
                       const float* __restrict__ outW, const float* __restrict__ outB) {
    int t = threadIdx.x;
    if (t < 4) {
        float s = 0.f, d = 0.f;
        for (int h = 0; h < 64; h++) {
            float w = gatW[t * 64 + h];
            s += w * attS[h];
            d += w * attD[h];
        }
        g_wscr[t] = s;
        g_wscr[4 + t] = d;
    }
    if (t < 48) {
        int f = t / 12, g = t % 12;
        float s = 0.f;
        for (int h = 0; h < 64; h++) s += gatW[f * 64 + h] * Wih[g * 64 + h];
        g_wscr[8 + t] = s;
    }
    if (t < 12) {
        float s = bih[t];
        for (int h = 0; h < 64; h++) s += gatB[h] * Wih[t * 64 + h];
        g_wscr[56 + t] = s;
    }
    // folded conv x linear: M[co,o,ci,kh,u] = sum_w outW[o,w]*convW[co,ci,kh,u-w+1]
    if (t < 576) {
        int co = t / 48, r = t % 48, o = r / 24, r2 = r % 24, ci = r2 / 3, kh = r2 % 3;
        float m[4] = {0.f, 0.f, 0.f, 0.f};
        for (int w = 0; w < 4; w++) {
            float oww = outW[o * 4 + w];
            for (int u = 0; u < 4; u++) {
                int kw = u - w + 1;
                if (kw >= 0 && kw < 3)
                    m[u] += oww * convW[((co * 8 + ci) * 3 + kh) * 3 + kw];
            }
        }
        g_cM[t] = make_float4(m[0], m[1], m[2], m[3]);
    }
    if (t < 24) {
        int co = t / 2, o = t % 2;
        float sw = outW[o * 4] + outW[o * 4 + 1] + outW[o * 4 + 2] + outW[o * 4 + 3];
        g_cB2[t] = outB[o] + convB[co] * sw;
    }
}

// ---------------- K0b: zero correction arrays ----------------
__global__ void k_zero() {
    int i = blockIdx.x * 256 + threadIdx.x;  // 131072 of them
    g_cS[i] = 0.f;
    ((float4*)g_cA)[i] = make_float4(0.f, 0.f, 0.f, 0.f);
}

// ---------------- K1: analytic full-mask softmax sums (sort + prefix + search) ----------------
__global__ __launch_bounds__(512) void k_sums(const float* __restrict__ x) {
    __shared__ float4 xs[NN];
    __shared__ float asrc[NN];
    __shared__ unsigned long long key[NN];
    __shared__ float s1[NN], s2[NN];
    __shared__ float4 P1[NN], P2[NN];

    int bt = blockIdx.x;
    int i = threadIdx.x;

    xs[i] = ((const float4*)x)[bt * NN + i];
    float vs0 = g_wscr[0], vs1 = g_wscr[1], vs2 = g_wscr[2], vs3 = g_wscr[3];
    float vd0 = g_wscr[4], vd1 = g_wscr[5], vd2 = g_wscr[6], vd3 = g_wscr[7];
    __syncthreads();

    float4 xi = xs[i];
    float a = xi.x * vs0 + xi.y * vs1 + xi.z * vs2 + xi.w * vs3;
    asrc[i] = a;
    key[i] = ((unsigned long long)fmono(a) << 32) | (unsigned)i;
    __syncthreads();

    // bitonic sort ascending
    for (int k = 2; k <= NN; k <<= 1) {
        for (int s = k >> 1; s > 0; s >>= 1) {
            int p = i ^ s;
            if (p > i) {
                unsigned long long A = key[i], Bv = key[p];
                bool up = ((i & k) == 0);
                if ((A > Bv) == up) { key[i] = Bv; key[p] = A; }
            }
            __syncthreads();
        }
    }

    int j = (int)(key[i] & 0xffffffffu);
    float aj = asrc[j];
    float e1 = ex2f(aj * L2E);
    float e2 = ex2f(aj * (0.2f * L2E));
    float4 xj = xs[j];
    s1[i] = e1; s2[i] = e2;
    P1[i] = make_float4(e1 * xj.x, e1 * xj.y, e1 * xj.z, e1 * xj.w);
    P2[i] = make_float4(e2 * xj.x, e2 * xj.y, e2 * xj.z, e2 * xj.w);
    __syncthreads();

    // inclusive prefix sums (Hillis-Steele)
    for (int off = 1; off < NN; off <<= 1) {
        float b1 = 0.f, b2 = 0.f;
        float4 q1 = make_float4(0.f, 0.f, 0.f, 0.f), q2 = q1;
        if (i >= off) { b1 = s1[i - off]; b2 = s2[i - off]; q1 = P1[i - off]; q2 = P2[i - off]; }
        __syncthreads();
        s1[i] += b1; s2[i] += b2;
        P1[i].x += q1.x; P1[i].y += q1.y; P1[i].z += q1.z; P1[i].w += q1.w;
        P2[i].x += q2.x; P2[i].y += q2.y; P2[i].z += q2.z; P2[i].w += q2.w;
        __syncthreads();
    }

    float s1t = s1[NN - 1];
    float4 P1t = P1[NN - 1];

    float ad = xi.x * vd0 + xi.y * vd1 + xi.z * vd2 + xi.w * vd3;
    unsigned int tu = fmono(-ad);
    // count of sorted asrc <= -ad (lo branch: u = ad+asrc <= 0 -> 0.2 slope)
    int lo = 0, hi = NN;
    while (lo < hi) {
        int mid = (lo + hi) >> 1;
        unsigned int kh = (unsigned int)(key[mid] >> 32);
        if (kh <= tu) lo = mid + 1; else hi = mid;
    }
    int cnt = lo;

    float l2 = 0.f, h1 = 0.f;
    float4 L2v = make_float4(0.f, 0.f, 0.f, 0.f), H1v = L2v;
    if (cnt > 0) { l2 = s2[cnt - 1]; h1 = s1[cnt - 1]; L2v = P2[cnt - 1]; H1v = P1[cnt - 1]; }

    float c1 = ex2f(ad * L2E);
    float c2 = ex2f(ad * (0.2f * L2E));
    float S = c2 * l2 + c1 * (s1t - h1);
    float4 Av = make_float4(c2 * L2v.x + c1 * (P1t.x - H1v.x),
                            c2 * L2v.y + c1 * (P1t.y - H1v.y),
                            c2 * L2v.z + c1 * (P1t.z - H1v.z),
                            c2 * L2v.w + c1 * (P1t.w - H1v.w));
    g_S[bt * NN + i] = S;
    g_A[bt * NN + i] = Av;
}

// ---------------- K2: stream adj, correct for (rare) exact zeros ----------------
// grid (16, B*T), block 256. Each block scans 64KB of adj. Pure DRAM-bound.
__global__ __launch_bounds__(256) void k_scan(const float* __restrict__ adj,
                                              const float* __restrict__ x) {
    int bt = blockIdx.y;
    int slice = blockIdx.x;
    int tid = threadIdx.x;
    const float4* ap = (const float4*)adj + (size_t)bt * (NN * NN / 4);
    int base = slice * 4096;

    float vs0 = g_wscr[0], vs1 = g_wscr[1], vs2 = g_wscr[2], vs3 = g_wscr[3];
    float vd0 = g_wscr[4], vd1 = g_wscr[5], vd2 = g_wscr[6], vd3 = g_wscr[7];

#pragma unroll
    for (int it = 0; it < 4; it++) {
        int q0 = base + it * 1024 + tid;
        float4 av[4];
#pragma unroll
        for (int k = 0; k < 4; k++) av[k] = ap[q0 + k * 256];
        float m[4];
#pragma unroll
        for (int k = 0; k < 4; k++)
            m[k] = fminf(fminf(fabsf(av[k].x), fabsf(av[k].y)),
                         fminf(fabsf(av[k].z), fabsf(av[k].w)));
        float mm = fminf(fminf(m[0], m[1]), fminf(m[2], m[3]));
        if (mm == 0.0f) {
            const float4* xb = (const float4*)x + bt * NN;
#pragma unroll
            for (int k = 0; k < 4; k++) {
                float vals[4] = {av[k].x, av[k].y, av[k].z, av[k].w};
                int q = q0 + k * 256;
                for (int c = 0; c < 4; c++) {
                    if (vals[c] == 0.0f) {
                        int lin = q * 4 + c;
                        int j = lin >> 9, col = lin & 511;
                        if (col != j) {
                            float4 xj = xb[j];
                            float4 xc = xb[col];
                            float as_ = xj.x * vs0 + xj.y * vs1 + xj.z * vs2 + xj.w * vs3;
                            float ad_ = xc.x * vd0 + xc.y * vd1 + xc.z * vd2 + xc.w * vd3;
                            float u = ad_ + as_;
                            float f = ex2f(fmaxf(u, 0.2f * u) * L2E);
                            int idx = bt * NN + col;
                            atomicAdd(&g_cS[idx], -f);
                            atomicAdd(&g_cA[idx * 4 + 0], -f * xj.x);
                            atomicAdd(&g_cA[idx * 4 + 1], -f * xj.y);
                            atomicAdd(&g_cA[idx * 4 + 2], -f * xj.z);
                            atomicAdd(&g_cA[idx * 4 + 3], -f * xj.w);
                        }
                    }
                }
            }
        }
    }
}

// ---------------- K3: combine + gates + GRU (hidden=4, view-bug sequence) ----------------
__global__ __launch_bounds__(256) void k_gru(const float* __restrict__ Whh,
                                             const float* __restrict__ bhh) {
    __shared__ float w[48], bb[12], wm[68];
    if (threadIdx.x < 48) w[threadIdx.x] = Whh[threadIdx.x];
    if (threadIdx.x < 12) bb[threadIdx.x] = bhh[threadIdx.x];
    if (threadIdx.x < 68) wm[threadIdx.x] = g_wscr[threadIdx.x];
    __syncthreads();

    int p = blockIdx.x * 256 + threadIdx.x;
    int b = p >> 9, rem = p & 511, t = rem >> 6, nhi = rem & 63;
    int bt = b * TT + t;

    float h[4] = {0.f, 0.f, 0.f, 0.f};

    for (int tt = 0; tt < 8; tt++) {
        int n = nhi * 8 + tt;
        int idx = bt * NN + n;
        float4 Av = g_A[idx];
        float S = g_S[idx] + g_cS[idx];
        float Ax = Av.x + g_cA[idx * 4 + 0];
        float Ay = Av.y + g_cA[idx * 4 + 1];
        float Az = Av.z + g_cA[idx * 4 + 2];
        float Aw = Av.w + g_cA[idx * 4 + 3];
        float inv = __fdividef(1.f, S);
        float ax0 = Ax * inv, ax1 = Ay * inv, ax2 = Az * inv, ax3 = Aw * inv;

        float gx[12];
#pragma unroll
        for (int g = 0; g < 12; g++)
            gx[g] = wm[56 + g] + ax0 * wm[8 + g] + ax1 * wm[20 + g] +
                    ax2 * wm[32 + g] + ax3 * wm[44 + g];

        float nh[4];
#pragma unroll
        for (int k = 0; k < 4; k++) {
            float ghr = bb[k]     + w[k * 4 + 0] * h[0] + w[k * 4 + 1] * h[1] + w[k * 4 + 2] * h[2] + w[k * 4 + 3] * h[3];
            float ghz = bb[4 + k] + w[(4 + k) * 4 + 0] * h[0] + w[(4 + k) * 4 + 1] * h[1] + w[(4 + k) * 4 + 2] * h[2] + w[(4 + k) * 4 + 3] * h[3];
            float ghn = bb[8 + k] + w[(8 + k) * 4 + 0] * h[0] + w[(8 + k) * 4 + 1] * h[1] + w[(8 + k) * 4 + 2] * h[2] + w[(8 + k) * 4 + 3] * h[3];
            float r = sigm(gx[k] + ghr);
            float z = sigm(gx[4 + k] + ghz);
            float nc = tanh_(gx[8 + k] + r * ghn);
            nh[k] = (1.f - z) * nc + z * h[k];
        }
#pragma unroll
        for (int k = 0; k < 4; k++) h[k] = nh[k];
        ((float4*)g_gru)[(b * TT + tt) * NN + t * 64 + nhi] =
            make_float4(h[0], h[1], h[2], h[3]);
    }
}

// ---------------- K4: folded Conv2d+Linear -> out[b,co,hp,{0,1}] ----------------
// grid 768 (= B*12co*2 halves), block 256. Weights staged per block (one co).
__global__ __launch_bounds__(256) void k_conv(float* __restrict__ out) {
    __shared__ float4 wM[48];
    __shared__ float b2[2];

    int half = blockIdx.x & 1;
    int plane = blockIdx.x >> 1;
    int co = plane % 12;
    int b = plane / 12;
    int tid = threadIdx.x;
    int hp = half * 256 + tid;

    if (tid < 48) wM[tid] = g_cM[co * 48 + tid];
    if (tid < 2) b2[tid] = g_cB2[co * 2 + tid];
    __syncthreads();

    float o0 = b2[0], o1 = b2[1];
    const float4* g4 = (const float4*)g_gru;

#pragma unroll
    for (int ci = 0; ci < 8; ci++) {
        int base = (b * TT + ci) * NN;
#pragma unroll
        for (int kh = 0; kh < 3; kh++) {
            int r = hp + kh - 1;
            float4 rv = make_float4(0.f, 0.f, 0.f, 0.f);
            if (r >= 0 && r < NN) rv = g4[base + r];
            float4 m0 = wM[ci * 3 + kh];
            float4 m1 = wM[24 + ci * 3 + kh];
            o0 += rv.x * m0.x + rv.y * m0.y + rv.z * m0.z + rv.w * m0.w;
            o1 += rv.x * m1.x + rv.y * m1.y + rv.z * m1.z + rv.w * m1.w;
        }
    }

    int idx = (b * COC + co) * NN + hp;
    out[2 * idx] = o0;
    out[2 * idx + 1] = o1;
}

extern "C" void kernel_launch(void* const* d_in, const int* in_sizes, int n_in,
                              void* d_out, int out_size) {
    const float* x    = (const float*)d_in[0];
    const float* adj  = (const float*)d_in[1];
    const float* gatW = (const float*)d_in[2];
    const float* attS = (const float*)d_in[3];
    const float* attD = (const float*)d_in[4];
    const float* gatB = (const float*)d_in[5];
    const float* Wih  = (const float*)d_in[6];
    const float* Whh  = (const float*)d_in[7];
    const float* bih  = (const float*)d_in[8];
    const float* bhh  = (const float*)d_in[9];
    const float* cW   = (const float*)d_in[10];
    const float* cB   = (const float*)d_in[11];
    const float* oW   = (const float*)d_in[12];
    const float* oB   = (const float*)d_in[13];
    float* out = (float*)d_out;

    k_prep<<<1, 576>>>(gatW, attS, attD, gatB, Wih, bih, cW, cB, oW, oB);
    k_zero<<<512, 256>>>();
    k_sums<<<BB * TT, 512>>>(x);
    dim3 gs(16, BB * TT);
    k_scan<<<gs, 256>>>(adj, x);
    k_gru<<<(BB * NN) / 256, 256>>>(Whh, bhh);
    k_conv<<<768, 256>>>(out);
}

// round 8
// speedup vs baseline: 1.0709x; 1.0709x over previous
#include <cuda_runtime.h>
#include <cuda_bf16.h>

#define BB 32
#define TT 8
#define NN 512
#define FF 4
#define COC 12
#define L2E 1.4426950408889634f

// Scratch (__device__ globals; no allocation allowed)
__device__ float  g_wscr[68];              // [0:4) v_src, [4:8) v_dst, [8:56) M[f*12+g], [56:68) cx
__device__ float4 g_A[BB * TT * NN];       // full-mask sum_j f*x_j
__device__ float  g_S[BB * TT * NN];       // full-mask sum_j f
__device__ float  g_cS[BB * TT * NN];      // corrections (rare zeros)
__device__ float  g_cA[BB * TT * NN * 4];
__device__ float  g_gru[BB * TT * NN * FF];// conv input [B][8ch][512][4]
__device__ float4 g_cM[576];               // folded conv+linear weights [co][o][ci][kh] -> float4 over u
__device__ float  g_cB2[24];               // folded bias [co][o]

__device__ __forceinline__ float ex2f(float a) {
    float r;
    asm("ex2.approx.f32 %0, %1;" : "=f"(r) : "f"(a));
    return r;
}
__device__ __forceinline__ float sigm(float x) {
    float e = ex2f(-x * L2E);
    return __fdividef(1.f, 1.f + e);
}
__device__ __forceinline__ float tanh_(float x) {
    float e = ex2f(x * (2.f * L2E));
    return __fdividef(e - 1.f, e + 1.f);
}
__device__ __forceinline__ unsigned int fmono(float f) {
    unsigned int u = __float_as_uint(f);
    return (u & 0x80000000u) ? ~u : (u | 0x80000000u);
}

// ---------------- K0: fold weights ----------------
__global__ void k_prep(const float* __restrict__ gatW, const float* __restrict__ attS,
                       const float* __restrict__ attD, const float* __restrict__ gatB,
                       const float* __restrict__ Wih, const float* __restrict__ bih,
                       const float* __restrict__ convW, const float* __restrict__ convB,
                       const float* __restrict__ outW, const float* __restrict__ outB) {
    int t = threadIdx.x;
    if (t < 4) {
        float s = 0.f, d = 0.f;
        for (int h = 0; h < 64; h++) {
            float w = gatW[t * 64 + h];
            s += w * attS[h];
            d += w * attD[h];
        }
        g_wscr[t] = s;
        g_wscr[4 + t] = d;
    }
    if (t < 48) {
        int f = t / 12, g = t % 12;
        float s = 0.f;
        for (int h = 0; h < 64; h++) s += gatW[f * 64 + h] * Wih[g * 64 + h];
        g_wscr[8 + t] = s;
    }
    if (t < 12) {
        float s = bih[t];
        for (int h = 0; h < 64; h++) s += gatB[h] * Wih[t * 64 + h];
        g_wscr[56 + t] = s;
    }
    // folded conv x linear: M[co,o,ci,kh,u] = sum_w outW[o,w]*convW[co,ci,kh,u-w+1]
    if (t < 576) {
        int co = t / 48, r = t % 48, o = r / 24, r2 = r % 24, ci = r2 / 3, kh = r2 % 3;
        float m[4] = {0.f, 0.f, 0.f, 0.f};
        for (int w = 0; w < 4; w++) {
            float oww = outW[o * 4 + w];
            for (int u = 0; u < 4; u++) {
                int kw = u - w + 1;
                if (kw >= 0 && kw < 3)
                    m[u] += oww * convW[((co * 8 + ci) * 3 + kh) * 3 + kw];
            }
        }
        g_cM[t] = make_float4(m[0], m[1], m[2], m[3]);
    }
    if (t < 24) {
        int co = t / 2, o = t % 2;
        float sw = outW[o * 4] + outW[o * 4 + 1] + outW[o * 4 + 2] + outW[o * 4 + 3];
        g_cB2[t] = outB[o] + convB[co] * sw;
    }
}

// ---------------- K1: analytic full-mask softmax sums (sort + shuffle-scan + search) ----------------
// Also zeroes the correction arrays (covers the (bt,i) domain exactly; ordered
// before k_scan by the kernel boundary).
__global__ __launch_bounds__(512) void k_sums(const float* __restrict__ x) {
    __shared__ float4 xs[NN];
    __shared__ float asrc[NN];
    __shared__ unsigned long long key[NN];
    __shared__ float s1[NN], s2[NN];
    __shared__ float4 P1[NN], P2[NN];
    __shared__ float wtot[16][10];

    int bt = blockIdx.x;
    int i = threadIdx.x;
    int lane = i & 31, wid = i >> 5;

    xs[i] = ((const float4*)x)[bt * NN + i];
    // zero corrections for this (bt,i)
    int gidx = bt * NN + i;
    g_cS[gidx] = 0.f;
    ((float4*)g_cA)[gidx] = make_float4(0.f, 0.f, 0.f, 0.f);

    float vs0 = g_wscr[0], vs1 = g_wscr[1], vs2 = g_wscr[2], vs3 = g_wscr[3];
    float vd0 = g_wscr[4], vd1 = g_wscr[5], vd2 = g_wscr[6], vd3 = g_wscr[7];
    __syncthreads();

    float4 xi = xs[i];
    float a = xi.x * vs0 + xi.y * vs1 + xi.z * vs2 + xi.w * vs3;
    asrc[i] = a;
    key[i] = ((unsigned long long)fmono(a) << 32) | (unsigned)i;
    __syncthreads();

    // bitonic sort ascending
    for (int k = 2; k <= NN; k <<= 1) {
        for (int s = k >> 1; s > 0; s >>= 1) {
            int p = i ^ s;
            if (p > i) {
                unsigned long long A = key[i], Bv = key[p];
                bool up = ((i & k) == 0);
                if ((A > Bv) == up) { key[i] = Bv; key[p] = A; }
            }
            __syncthreads();
        }
    }

    int j = (int)(key[i] & 0xffffffffu);
    float aj = asrc[j];
    float e1 = ex2f(aj * L2E);
    float e2 = ex2f(aj * (0.2f * L2E));
    float4 xj = xs[j];
    float v[10] = {e1, e2,
                   e1 * xj.x, e1 * xj.y, e1 * xj.z, e1 * xj.w,
                   e2 * xj.x, e2 * xj.y, e2 * xj.z, e2 * xj.w};

    // warp-level inclusive scan (registers, no smem)
#pragma unroll
    for (int off = 1; off < 32; off <<= 1) {
        float t[10];
#pragma unroll
        for (int k = 0; k < 10; k++) t[k] = __shfl_up_sync(0xffffffffu, v[k], off);
        if (lane >= off) {
#pragma unroll
            for (int k = 0; k < 10; k++) v[k] += t[k];
        }
    }
    if (lane == 31) {
#pragma unroll
        for (int k = 0; k < 10; k++) wtot[wid][k] = v[k];
    }
    __syncthreads();
    if (wid == 0 && lane < 16) {
        float w_[10];
#pragma unroll
        for (int k = 0; k < 10; k++) w_[k] = wtot[lane][k];
#pragma unroll
        for (int off = 1; off < 16; off <<= 1) {
            float t[10];
#pragma unroll
            for (int k = 0; k < 10; k++) t[k] = __shfl_up_sync(0xffffu, w_[k], off);
            if (lane >= off) {
#pragma unroll
                for (int k = 0; k < 10; k++) w_[k] += t[k];
            }
        }
#pragma unroll
        for (int k = 0; k < 10; k++) wtot[lane][k] = w_[k];
    }
    __syncthreads();
    if (wid > 0) {
#pragma unroll
        for (int k = 0; k < 10; k++) v[k] += wtot[wid - 1][k];
    }
    s1[i] = v[0];
    s2[i] = v[1];
    P1[i] = make_float4(v[2], v[3], v[4], v[5]);
    P2[i] = make_float4(v[6], v[7], v[8], v[9]);
    __syncthreads();

    float s1t = s1[NN - 1];
    float4 P1t = P1[NN - 1];

    float ad = xi.x * vd0 + xi.y * vd1 + xi.z * vd2 + xi.w * vd3;
    unsigned int tu = fmono(-ad);
    // count of sorted asrc <= -ad (lo branch: u = ad+asrc <= 0 -> 0.2 slope)
    int lo = 0, hi = NN;
    while (lo < hi) {
        int mid = (lo + hi) >> 1;
        unsigned int kh = (unsigned int)(key[mid] >> 32);
        if (kh <= tu) lo = mid + 1; else hi = mid;
    }
    int cnt = lo;

    float l2 = 0.f, h1 = 0.f;
    float4 L2v = make_float4(0.f, 0.f, 0.f, 0.f), H1v = L2v;
    if (cnt > 0) { l2 = s2[cnt - 1]; h1 = s1[cnt - 1]; L2v = P2[cnt - 1]; H1v = P1[cnt - 1]; }

    float c1 = ex2f(ad * L2E);
    float c2 = ex2f(ad * (0.2f * L2E));
    float S = c2 * l2 + c1 * (s1t - h1);
    float4 Av = make_float4(c2 * L2v.x + c1 * (P1t.x - H1v.x),
                            c2 * L2v.y + c1 * (P1t.y - H1v.y),
                            c2 * L2v.z + c1 * (P1t.z - H1v.z),
                            c2 * L2v.w + c1 * (P1t.w - H1v.w));
    g_S[gidx] = S;
    g_A[gidx] = Av;
}

// ---------------- K2: stream adj, correct for (rare) exact zeros ----------------
// grid (16, B*T), block 256. Each block scans 64KB of adj. Pure DRAM-bound.
__global__ __launch_bounds__(256) void k_scan(const float* __restrict__ adj,
                                              const float* __restrict__ x) {
    int bt = blockIdx.y;
    int slice = blockIdx.x;
    int tid = threadIdx.x;
    const float4* ap = (const float4*)adj + (size_t)bt * (NN * NN / 4);
    int base = slice * 4096;

    float vs0 = g_wscr[0], vs1 = g_wscr[1], vs2 = g_wscr[2], vs3 = g_wscr[3];
    float vd0 = g_wscr[4], vd1 = g_wscr[5], vd2 = g_wscr[6], vd3 = g_wscr[7];

#pragma unroll
    for (int it = 0; it < 4; it++) {
        int q0 = base + it * 1024 + tid;
        float4 av[4];
#pragma unroll
        for (int k = 0; k < 4; k++) av[k] = ap[q0 + k * 256];
        float m[4];
#pragma unroll
        for (int k = 0; k < 4; k++)
            m[k] = fminf(fminf(fabsf(av[k].x), fabsf(av[k].y)),
                         fminf(fabsf(av[k].z), fabsf(av[k].w)));
        float mm = fminf(fminf(m[0], m[1]), fminf(m[2], m[3]));
        if (mm == 0.0f) {
            const float4* xb = (const float4*)x + bt * NN;
#pragma unroll
            for (int k = 0; k < 4; k++) {
                float vals[4] = {av[k].x, av[k].y, av[k].z, av[k].w};
                int q = q0 + k * 256;
                for (int c = 0; c < 4; c++) {
                    if (vals[c] == 0.0f) {
                        int lin = q * 4 + c;
                        int j = lin >> 9, col = lin & 511;
                        if (col != j) {
                            float4 xj = xb[j];
                            float4 xc = xb[col];
                            float as_ = xj.x * vs0 + xj.y * vs1 + xj.z * vs2 + xj.w * vs3;
                            float ad_ = xc.x * vd0 + xc.y * vd1 + xc.z * vd2 + xc.w * vd3;
                            float u = ad_ + as_;
                            float f = ex2f(fmaxf(u, 0.2f * u) * L2E);
                            int idx = bt * NN + col;
                            atomicAdd(&g_cS[idx], -f);
                            atomicAdd(&g_cA[idx * 4 + 0], -f * xj.x);
                            atomicAdd(&g_cA[idx * 4 + 1], -f * xj.y);
                            atomicAdd(&g_cA[idx * 4 + 2], -f * xj.z);
                            atomicAdd(&g_cA[idx * 4 + 3], -f * xj.w);
                        }
                    }
                }
            }
        }
    }
}

// ---------------- K3: combine + gates + GRU (hidden=4, view-bug sequence) ----------------
__global__ __launch_bounds__(256) void k_gru(const float* __restrict__ Whh,
                                             const float* __restrict__ bhh) {
    __shared__ float w[48], bb[12], wm[68];
    if (threadIdx.x < 48) w[threadIdx.x] = Whh[threadIdx.x];
    if (threadIdx.x < 12) bb[threadIdx.x] = bhh[threadIdx.x];
    if (threadIdx.x < 68) wm[threadIdx.x] = g_wscr[threadIdx.x];
    __syncthreads();

    int p = blockIdx.x * 256 + threadIdx.x;
    int b = p >> 9, rem = p & 511, t = rem >> 6, nhi = rem & 63;
    int bt = b * TT + t;

    float h[4] = {0.f, 0.f, 0.f, 0.f};

    for (int tt = 0; tt < 8; tt++) {
        int n = nhi * 8 + tt;
        int idx = bt * NN + n;
        float4 Av = g_A[idx];
        float S = g_S[idx] + g_cS[idx];
        float Ax = Av.x + g_cA[idx * 4 + 0];
        float Ay = Av.y + g_cA[idx * 4 + 1];
        float Az = Av.z + g_cA[idx * 4 + 2];
        float Aw = Av.w + g_cA[idx * 4 + 3];
        float inv = __fdividef(1.f, S);
        float ax0 = Ax * inv, ax1 = Ay * inv, ax2 = Az * inv, ax3 = Aw * inv;

        float gx[12];
#pragma unroll
        for (int g = 0; g < 12; g++)
            gx[g] = wm[56 + g] + ax0 * wm[8 + g] + ax1 * wm[20 + g] +
                    ax2 * wm[32 + g] + ax3 * wm[44 + g];

        float nh[4];
#pragma unroll
        for (int k = 0; k < 4; k++) {
            float ghr = bb[k]     + w[k * 4 + 0] * h[0] + w[k * 4 + 1] * h[1] + w[k * 4 + 2] * h[2] + w[k * 4 + 3] * h[3];
            float ghz = bb[4 + k] + w[(4 + k) * 4 + 0] * h[0] + w[(4 + k) * 4 + 1] * h[1] + w[(4 + k) * 4 + 2] * h[2] + w[(4 + k) * 4 + 3] * h[3];
            float ghn = bb[8 + k] + w[(8 + k) * 4 + 0] * h[0] + w[(8 + k) * 4 + 1] * h[1] + w[(8 + k) * 4 + 2] * h[2] + w[(8 + k) * 4 + 3] * h[3];
            float r = sigm(gx[k] + ghr);
            float z = sigm(gx[4 + k] + ghz);
            float nc = tanh_(gx[8 + k] + r * ghn);
            nh[k] = (1.f - z) * nc + z * h[k];
        }
#pragma unroll
        for (int k = 0; k < 4; k++) h[k] = nh[k];
        ((float4*)g_gru)[(b * TT + tt) * NN + t * 64 + nhi] =
            make_float4(h[0], h[1], h[2], h[3]);
    }
}

// ---------------- K4: folded Conv2d+Linear -> out[b,co,hp,{0,1}] ----------------
// grid 768 (= B*12co*2 halves), block 256. Weights staged per block (one co).
__global__ __launch_bounds__(256) void k_conv(float* __restrict__ out) {
    __shared__ float4 wM[48];
    __shared__ float b2[2];

    int half = blockIdx.x & 1;
    int plane = blockIdx.x >> 1;
    int co = plane % 12;
    int b = plane / 12;
    int tid = threadIdx.x;
    int hp = half * 256 + tid;

    if (tid < 48) wM[tid] = g_cM[co * 48 + tid];
    if (tid < 2) b2[tid] = g_cB2[co * 2 + tid];
    __syncthreads();

    float o0 = b2[0], o1 = b2[1];
    const float4* g4 = (const float4*)g_gru;

#pragma unroll
    for (int ci = 0; ci < 8; ci++) {
        int base = (b * TT + ci) * NN;
#pragma unroll
        for (int kh = 0; kh < 3; kh++) {
            int r = hp + kh - 1;
            float4 rv = make_float4(0.f, 0.f, 0.f, 0.f);
            if (r >= 0 && r < NN) rv = g4[base + r];
            float4 m0 = wM[ci * 3 + kh];
            float4 m1 = wM[24 + ci * 3 + kh];
            o0 += rv.x * m0.x + rv.y * m0.y + rv.z * m0.z + rv.w * m0.w;
            o1 += rv.x * m1.x + rv.y * m1.y + rv.z * m1.z + rv.w * m1.w;
        }
    }

    int idx = (b * COC + co) * NN + hp;
    out[2 * idx] = o0;
    out[2 * idx + 1] = o1;
}

extern "C" void kernel_launch(void* const* d_in, const int* in_sizes, int n_in,
                              void* d_out, int out_size) {
    const float* x    = (const float*)d_in[0];
    const float* adj  = (const float*)d_in[1];
    const float* gatW = (const float*)d_in[2];
    const float* attS = (const float*)d_in[3];
    const float* attD = (const float*)d_in[4];
    const float* gatB = (const float*)d_in[5];
    const float* Wih  = (const float*)d_in[6];
    const float* Whh  = (const float*)d_in[7];
    const float* bih  = (const float*)d_in[8];
    const float* bhh  = (const float*)d_in[9];
    const float* cW   = (const float*)d_in[10];
    const float* cB   = (const float*)d_in[11];
    const float* oW   = (const float*)d_in[12];
    const float* oB   = (const float*)d_in[13];
    float* out = (float*)d_out;

    k_prep<<<1, 576>>>(gatW, attS, attD, gatB, Wih, bih, cW, cB, oW, oB);
    k_sums<<<BB * TT, 512>>>(x);
    dim3 gs(16, BB * TT);
    k_scan<<<gs, 256>>>(adj, x);
    k_gru<<<(BB * NN) / 256, 256>>>(Whh, bhh);
    k_conv<<<768, 256>>>(out);
}

// round 10
// speedup vs baseline: 1.2277x; 1.1465x over previous
#include <cuda_runtime.h>
#include <cuda_bf16.h>

#define BB 32
#define TT 8
#define NN 512
#define FF 4
#define COC 12
#define L2E 1.4426950408889634f

// Scratch (__device__ globals; no allocation allowed)
__device__ float  g_wscr[68];              // [0:4) v_src, [4:8) v_dst, [8:56) M[f*12+g], [56:68) cx
__device__ float4 g_A[BB * TT * NN];       // full-mask sum_j f*x_j
__device__ float  g_S[BB * TT * NN];       // full-mask sum_j f
__device__ float  g_cS[BB * TT * NN];      // corrections (rare zeros)
__device__ float  g_cA[BB * TT * NN * 4];
__device__ float  g_gru[BB * TT * NN * FF];// conv input [B][8ch][512][4]
__device__ float4 g_cM[576];               // folded conv+linear weights
__device__ float  g_cB2[24];               // folded bias [co][o]

__device__ __forceinline__ float ex2f(float a) {
    float r;
    asm("ex2.approx.f32 %0, %1;" : "=f"(r) : "f"(a));
    return r;
}
__device__ __forceinline__ float sigm(float x) {
    float e = ex2f(-x * L2E);
    return __fdividef(1.f, 1.f + e);
}
__device__ __forceinline__ float tanh_(float x) {
    float e = ex2f(x * (2.f * L2E));
    return __fdividef(e - 1.f, e + 1.f);
}
__device__ __forceinline__ unsigned int fmono(float f) {
    unsigned int u = __float_as_uint(f);
    return (u & 0x80000000u) ? ~u : (u | 0x80000000u);
}

// ---------------- K0: fold weights (block 0) + zero corrections (all blocks) ----------------
__global__ __launch_bounds__(576) void k_prep(const float* __restrict__ gatW, const float* __restrict__ attS,
                       const float* __restrict__ attD, const float* __restrict__ gatB,
                       const float* __restrict__ Wih, const float* __restrict__ bih,
                       const float* __restrict__ convW, const float* __restrict__ convB,
                       const float* __restrict__ outW, const float* __restrict__ outB) {
    int t = threadIdx.x;
    int zi = blockIdx.x * 576 + t;
    if (zi < BB * TT * NN) {
        g_cS[zi] = 0.f;
        ((float4*)g_cA)[zi] = make_float4(0.f, 0.f, 0.f, 0.f);
    }
    if (blockIdx.x != 0) return;

    if (t < 4) {
        float s = 0.f, d = 0.f;
        for (int h = 0; h < 64; h++) {
            float w = gatW[t * 64 + h];
            s += w * attS[h];
            d += w * attD[h];
        }
        g_wscr[t] = s;
        g_wscr[4 + t] = d;
    }
    if (t < 48) {
        int f = t / 12, g = t % 12;
        float s = 0.f;
        for (int h = 0; h < 64; h++) s += gatW[f * 64 + h] * Wih[g * 64 + h];
        g_wscr[8 + t] = s;
    }
    if (t < 12) {
        float s = bih[t];
        for (int h = 0; h < 64; h++) s += gatB[h] * Wih[t * 64 + h];
        g_wscr[56 + t] = s;
    }
    // folded conv x linear: M[co,o,ci,kh,u] = sum_w outW[o,w]*convW[co,ci,kh,u-w+1]
    if (t < 576) {
        int co = t / 48, r = t % 48, o = r / 24, r2 = r % 24, ci = r2 / 3, kh = r2 % 3;
        float m[4] = {0.f, 0.f, 0.f, 0.f};
        for (int w = 0; w < 4; w++) {
            float oww = outW[o * 4 + w];
            for (int u = 0; u < 4; u++) {
                int kw = u - w + 1;
                if (kw >= 0 && kw < 3)
                    m[u] += oww * convW[((co * 8 + ci) * 3 + kh) * 3 + kw];
            }
        }
        g_cM[t] = make_float4(m[0], m[1], m[2], m[3]);
    }
    if (t < 24) {
        int co = t / 2, o = t % 2;
        float sw = outW[o * 4] + outW[o * 4 + 1] + outW[o * 4 + 2] + outW[o * 4 + 3];
        g_cB2[t] = outB[o] + convB[co] * sw;
    }
}

// ---------------- K1 (fused): adj zero-scan (slices 0-7) + analytic sums (slice 8) ----------------
// grid (9, B*T), block 512. Scan part is DRAM-bound; sums part rides the idle issue slots.
__global__ __launch_bounds__(512) void k_scan(const float* __restrict__ adj,
                                              const float* __restrict__ x) {
    __shared__ float4 xs[NN];
    __shared__ float asrc[NN];
    __shared__ unsigned long long key[NN];
    __shared__ float s1[NN], s2[NN];
    __shared__ float4 P1[NN], P2[NN];
    __shared__ float wtot[16][10];

    int bt = blockIdx.y;
    int slice = blockIdx.x;
    int tid = threadIdx.x;

    float vs0 = g_wscr[0], vs1 = g_wscr[1], vs2 = g_wscr[2], vs3 = g_wscr[3];
    float vd0 = g_wscr[4], vd1 = g_wscr[5], vd2 = g_wscr[6], vd3 = g_wscr[7];

    if (slice < 8) {
        // ---- adj streaming: 512 threads, 128KB per block ----
        const float4* ap = (const float4*)adj + (size_t)bt * (NN * NN / 4);
        int base = slice * 8192;
#pragma unroll
        for (int it = 0; it < 4; it++) {
            int q0 = base + it * 2048 + tid;
            float4 av[4];
#pragma unroll
            for (int k = 0; k < 4; k++) av[k] = ap[q0 + k * 512];
            float m[4];
#pragma unroll
            for (int k = 0; k < 4; k++)
                m[k] = fminf(fminf(fabsf(av[k].x), fabsf(av[k].y)),
                             fminf(fabsf(av[k].z), fabsf(av[k].w)));
            float mm = fminf(fminf(m[0], m[1]), fminf(m[2], m[3]));
            if (mm == 0.0f) {
                const float4* xb = (const float4*)x + bt * NN;
#pragma unroll
                for (int k = 0; k < 4; k++) {
                    float vals[4] = {av[k].x, av[k].y, av[k].z, av[k].w};
                    int q = q0 + k * 512;
                    for (int c = 0; c < 4; c++) {
                        if (vals[c] == 0.0f) {
                            int lin = q * 4 + c;
                            int j = lin >> 9, col = lin & 511;
                            if (col != j) {
                                float4 xj = xb[j];
                                float4 xc = xb[col];
                                float as_ = xj.x * vs0 + xj.y * vs1 + xj.z * vs2 + xj.w * vs3;
                                float ad_ = xc.x * vd0 + xc.y * vd1 + xc.z * vd2 + xc.w * vd3;
                                float u = ad_ + as_;
                                float f = ex2f(fmaxf(u, 0.2f * u) * L2E);
                                int idx = bt * NN + col;
                                atomicAdd(&g_cS[idx], -f);
                                atomicAdd(&g_cA[idx * 4 + 0], -f * xj.x);
                                atomicAdd(&g_cA[idx * 4 + 1], -f * xj.y);
                                atomicAdd(&g_cA[idx * 4 + 2], -f * xj.z);
                                atomicAdd(&g_cA[idx * 4 + 3], -f * xj.w);
                            }
                        }
                    }
                }
            }
        }
        return;
    }

    // ---- sums: sort + shuffle-scan + binary search (512 threads, one per row) ----
    int i = tid;
    int lane = i & 31, wid = i >> 5;
    int gidx = bt * NN + i;

    xs[i] = ((const float4*)x)[gidx];
    __syncthreads();

    float4 xi = xs[i];
    float a = xi.x * vs0 + xi.y * vs1 + xi.z * vs2 + xi.w * vs3;
    asrc[i] = a;
    key[i] = ((unsigned long long)fmono(a) << 32) | (unsigned)i;
    __syncthreads();

    // bitonic sort ascending
    for (int k = 2; k <= NN; k <<= 1) {
        for (int s = k >> 1; s > 0; s >>= 1) {
            int p = i ^ s;
            if (p > i) {
                unsigned long long A = key[i], Bv = key[p];
                bool up = ((i & k) == 0);
                if ((A > Bv) == up) { key[i] = Bv; key[p] = A; }
            }
            __syncthreads();
        }
    }

    int j = (int)(key[i] & 0xffffffffu);
    float aj = asrc[j];
    float e1 = ex2f(aj * L2E);
    float e2 = ex2f(aj * (0.2f * L2E));
    float4 xj = xs[j];
    float v[10] = {e1, e2,
                   e1 * xj.x, e1 * xj.y, e1 * xj.z, e1 * xj.w,
                   e2 * xj.x, e2 * xj.y, e2 * xj.z, e2 * xj.w};

#pragma unroll
    for (int off = 1; off < 32; off <<= 1) {
        float t[10];
#pragma unroll
        for (int k = 0; k < 10; k++) t[k] = __shfl_up_sync(0xffffffffu, v[k], off);
        if (lane >= off) {
#pragma unroll
            for (int k = 0; k < 10; k++) v[k] += t[k];
        }
    }
    if (lane == 31) {
#pragma unroll
        for (int k = 0; k < 10; k++) wtot[wid][k] = v[k];
    }
    __syncthreads();
    if (wid == 0 && lane < 16) {
        float w_[10];
#pragma unroll
        for (int k = 0; k < 10; k++) w_[k] = wtot[lane][k];
#pragma unroll
        for (int off = 1; off < 16; off <<= 1) {
            float t[10];
#pragma unroll
            for (int k = 0; k < 10; k++) t[k] = __shfl_up_sync(0xffffu, w_[k], off);
            if (lane >= off) {
#pragma unroll
                for (int k = 0; k < 10; k++) w_[k] += t[k];
            }
        }
#pragma unroll
        for (int k = 0; k < 10; k++) wtot[lane][k] = w_[k];
    }
    __syncthreads();
    if (wid > 0) {
#pragma unroll
        for (int k = 0; k < 10; k++) v[k] += wtot[wid - 1][k];
    }
    s1[i] = v[0];
    s2[i] = v[1];
    P1[i] = make_float4(v[2], v[3], v[4], v[5]);
    P2[i] = make_float4(v[6], v[7], v[8], v[9]);
    __syncthreads();

    float s1t = s1[NN - 1];
    float4 P1t = P1[NN - 1];

    float ad = xi.x * vd0 + xi.y * vd1 + xi.z * vd2 + xi.w * vd3;
    unsigned int tu = fmono(-ad);
    int lo = 0, hi = NN;
    while (lo < hi) {
        int mid = (lo + hi) >> 1;
        unsigned int kh = (unsigned int)(key[mid] >> 32);
        if (kh <= tu) lo = mid + 1; else hi = mid;
    }
    int cnt = lo;

    float l2 = 0.f, h1 = 0.f;
    float4 L2v = make_float4(0.f, 0.f, 0.f, 0.f), H1v = L2v;
    if (cnt > 0) { l2 = s2[cnt - 1]; h1 = s1[cnt - 1]; L2v = P2[cnt - 1]; H1v = P1[cnt - 1]; }

    float c1 = ex2f(ad * L2E);
    float c2 = ex2f(ad * (0.2f * L2E));
    float S = c2 * l2 + c1 * (s1t - h1);
    float4 Av = make_float4(c2 * L2v.x + c1 * (P1t.x - H1v.x),
                            c2 * L2v.y + c1 * (P1t.y - H1v.y),
                            c2 * L2v.z + c1 * (P1t.z - H1v.z),
                            c2 * L2v.w + c1 * (P1t.w - H1v.w));
    g_S[gidx] = S;
    g_A[gidx] = Av;
}

// ---------------- K2: lane-parallel GRU (4 threads per sequence) ----------------
// Thread k of a 4-lane group owns h[k]. ax/h all-to-all via width-4 shuffles.
__global__ __launch_bounds__(256) void k_gru(const float* __restrict__ Whh,
                                             const float* __restrict__ bhh) {
    __shared__ float w[48], bb[12], wm[68];
    if (threadIdx.x < 48) w[threadIdx.x] = Whh[threadIdx.x];
    if (threadIdx.x < 12) bb[threadIdx.x] = bhh[threadIdx.x];
    if (threadIdx.x < 68) wm[threadIdx.x] = g_wscr[threadIdx.x];
    __syncthreads();

    int q = blockIdx.x * 256 + threadIdx.x;   // 65536 threads
    int p = q >> 2, k = q & 3;
    int b = p >> 9, rem = p & 511, t = rem >> 6, nhi = rem & 63;
    int bt = b * TT + t;

    // this lane's gate rows
    float wr0 = w[k * 4 + 0], wr1 = w[k * 4 + 1], wr2 = w[k * 4 + 2], wr3 = w[k * 4 + 3];
    float wz0 = w[(4 + k) * 4 + 0], wz1 = w[(4 + k) * 4 + 1], wz2 = w[(4 + k) * 4 + 2], wz3 = w[(4 + k) * 4 + 3];
    float wn0 = w[(8 + k) * 4 + 0], wn1 = w[(8 + k) * 4 + 1], wn2 = w[(8 + k) * 4 + 2], wn3 = w[(8 + k) * 4 + 3];
    float br = bb[k], bz = bb[4 + k], bn = bb[8 + k];
    float m0r = wm[8 + 0 * 12 + k],  m1r = wm[8 + 1 * 12 + k],  m2r = wm[8 + 2 * 12 + k],  m3r = wm[8 + 3 * 12 + k];
    float m0z = wm[8 + 0 * 12 + 4 + k], m1z = wm[8 + 1 * 12 + 4 + k], m2z = wm[8 + 2 * 12 + 4 + k], m3z = wm[8 + 3 * 12 + 4 + k];
    float m0n = wm[8 + 0 * 12 + 8 + k], m1n = wm[8 + 1 * 12 + 8 + k], m2n = wm[8 + 2 * 12 + 8 + k], m3n = wm[8 + 3 * 12 + 8 + k];
    float cr = wm[56 + k], cz = wm[60 + k], cn = wm[64 + k];

    float h = 0.f;

    for (int tt = 0; tt < 8; tt++) {
        int n = nhi * 8 + tt;
        int idx = bt * NN + n;
        float Ak = ((const float*)g_A)[idx * 4 + k] + g_cA[idx * 4 + k];
        float S = g_S[idx] + g_cS[idx];
        float axk = Ak * __fdividef(1.f, S);
        float ax0 = __shfl_sync(0xffffffffu, axk, 0, 4);
        float ax1 = __shfl_sync(0xffffffffu, axk, 1, 4);
        float ax2 = __shfl_sync(0xffffffffu, axk, 2, 4);
        float ax3 = __shfl_sync(0xffffffffu, axk, 3, 4);

        float gxr = cr + ax0 * m0r + ax1 * m1r + ax2 * m2r + ax3 * m3r;
        float gxz = cz + ax0 * m0z + ax1 * m1z + ax2 * m2z + ax3 * m3z;
        float gxn = cn + ax0 * m0n + ax1 * m1n + ax2 * m2n + ax3 * m3n;

        float h0 = __shfl_sync(0xffffffffu, h, 0, 4);
        float h1 = __shfl_sync(0xffffffffu, h, 1, 4);
        float h2 = __shfl_sync(0xffffffffu, h, 2, 4);
        float h3 = __shfl_sync(0xffffffffu, h, 3, 4);

        float ghr = br + wr0 * h0 + wr1 * h1 + wr2 * h2 + wr3 * h3;
        float ghz = bz + wz0 * h0 + wz1 * h1 + wz2 * h2 + wz3 * h3;
        float ghn = bn + wn0 * h0 + wn1 * h1 + wn2 * h2 + wn3 * h3;

        float r = sigm(gxr + ghr);
        float z = sigm(gxz + ghz);
        float nc = tanh_(gxn + r * ghn);
        h = (1.f - z) * nc + z * h;

        g_gru[(((b * TT + tt) * NN) + t * 64 + nhi) * 4 + k] = h;
    }
}

// ---------------- K3: folded Conv2d+Linear -> out[b,co,hp,{0,1}] ----------------
__global__ __launch_bounds__(256) void k_conv(float* __restrict__ out) {
    __shared__ float4 wM[48];
    __shared__ float b2[2];

    int half = blockIdx.x & 1;
    int plane = blockIdx.x >> 1;
    int co = plane % 12;
    int b = plane / 12;
    int tid = threadIdx.x;
    int hp = half * 256 + tid;

    if (tid < 48) wM[tid] = g_cM[co * 48 + tid];
    if (tid < 2) b2[tid] = g_cB2[co * 2 + tid];
    __syncthreads();

    float o0 = b2[0], o1 = b2[1];
    const float4* g4 = (const float4*)g_gru;

#pragma unroll
    for (int ci = 0; ci < 8; ci++) {
        int base = (b * TT + ci) * NN;
#pragma unroll
        for (int kh = 0; kh < 3; kh++) {
            int r = hp + kh - 1;
            float4 rv = make_float4(0.f, 0.f, 0.f, 0.f);
            if (r >= 0 && r < NN) rv = g4[base + r];
            float4 m0 = wM[ci * 3 + kh];
            float4 m1 = wM[24 + ci * 3 + kh];
            o0 += rv.x * m0.x + rv.y * m0.y + rv.z * m0.z + rv.w * m0.w;
            o1 += rv.x * m1.x + rv.y * m1.y + rv.z * m1.z + rv.w * m1.w;
        }
    }

    int idx = (b * COC + co) * NN + hp;
    out[2 * idx] = o0;
    out[2 * idx + 1] = o1;
}

extern "C" void kernel_launch(void* const* d_in, const int* in_sizes, int n_in,
                              void* d_out, int out_size) {
    const float* x    = (const float*)d_in[0];
    const float* adj  = (const float*)d_in[1];
    const float* gatW = (const float*)d_in[2];
    const float* attS = (const float*)d_in[3];
    const float* attD = (const float*)d_in[4];
    const float* gatB = (const float*)d_in[5];
    const float* Wih  = (const float*)d_in[6];
    const float* Whh  = (const float*)d_in[7];
    const float* bih  = (const float*)d_in[8];
    const float* bhh  = (const float*)d_in[9];
    const float* cW   = (const float*)d_in[10];
    const float* cB   = (const float*)d_in[11];
    const float* oW   = (const float*)d_in[12];
    const float* oB   = (const float*)d_in[13];
    float* out = (float*)d_out;

    k_prep<<<256, 576>>>(gatW, attS, attD, gatB, Wih, bih, cW, cB, oW, oB);
    dim3 gs(9, BB * TT);
    k_scan<<<gs, 512>>>(adj, x);
    k_gru<<<256, 256>>>(Whh, bhh);
    k_conv<<<768, 256>>>(out);
}